// round 13
// baseline (speedup 1.0000x reference)
#include <cuda_runtime.h>
#include <cuda_fp16.h>
#include <math.h>

#define BB 64
#define TT 128
#define DD 256
#define HH 1024
#define NCTA 128
#define NTHR 512
#define NKW 4
#define CHH 64                   // k-chunk (halves) per kw per stage
#define SROW_H 72                // smem row stride in halves (144B, conflict-free)
#define STAGE_H (NKW*96*SROW_H)  // 27648 halves per stage
#define RED_BYTE_OFF (3*STAGE_H*2)            // 165888 B
#define SMEM_BYTES (RED_BYTE_OFF + 6144*4)    // + 24KB fp32 reduce scratch

// ------------------------- device globals -------------------------
__device__ __half g_WP1[NCTA*26*HH];  // per-CTA: 24 Whh0 i/g/o rows + 2 Wout rows
__device__ __half g_WP2[NCTA*24*DD];  // per-CTA Wih0 i/g/o rows
__device__ __half g_WP3[NCTA*24*HH];  // per-CTA (Wih1+Whh1) i/g/o rows
__device__ float  g_B0[NCTA*24];
__device__ float  g_B1[NCTA*24];
__device__ __half g_h[BB*HH];
__device__ __half g_h0[BB*HH];
__device__ __half g_imp[BB*DD];
__device__ float  g_hf[BB*HH];        // fp32 h_final (written at t==TT-1)
__device__ unsigned g_barcnt;

// ------------------------- helpers -------------------------
__device__ __forceinline__ void mma_f16(float* d, const unsigned* a, const unsigned* b) {
    asm volatile(
        "mma.sync.aligned.m16n8k16.row.col.f32.f16.f16.f32 "
        "{%0,%1,%2,%3},{%4,%5,%6,%7},{%8,%9},{%0,%1,%2,%3};"
        : "+f"(d[0]), "+f"(d[1]), "+f"(d[2]), "+f"(d[3])
        : "r"(a[0]), "r"(a[1]), "r"(a[2]), "r"(a[3]), "r"(b[0]), "r"(b[1]));
}
__device__ __forceinline__ void cpa16(unsigned s, const void* g) {
    asm volatile("cp.async.cg.shared.global [%0], [%1], 16;" :: "r"(s), "l"(g));
}
__device__ __forceinline__ void cpcommit() { asm volatile("cp.async.commit_group;"); }

__device__ __forceinline__ int As_idx(int st, int kw, int row, int k) {   // halves
    return st * STAGE_H + (kw * 96 + row) * SROW_H + k;
}
__device__ __forceinline__ int Ws_idx(int st, int kw, int row, int k) {
    return st * STAGE_H + (kw * 96 + 64 + row) * SROW_H + k;
}

// ------------------------- pack kernel -------------------------
__device__ __forceinline__ int phys_row(int cta, int r) {  // r in [0,24)
    int u = cta * 8 + (r & 7);
    int g = r >> 3;
    return u + (g == 0 ? 0 : (g == 1 ? 2048 : 3072));
}
#define N1 (NCTA*26*HH)
#define N2 (NCTA*24*DD)
#define N3 (NCTA*24*HH)
#define NBv (NCTA*24)
#define NHh (BB*HH)
#define PACK_TOT (N1+N2+N3+NBv+NHh)

__global__ void pack_all(const float* __restrict__ Wih0, const float* __restrict__ Whh0,
                         const float* __restrict__ bih0, const float* __restrict__ bhh0,
                         const float* __restrict__ Wih1, const float* __restrict__ Whh1,
                         const float* __restrict__ bih1, const float* __restrict__ bhh1,
                         const float* __restrict__ Wout) {
    int idx = blockIdx.x * 256 + threadIdx.x;
    if (idx < N1) {
        int cta = idx / 26624, rem = idx % 26624;
        int r = rem >> 10, k = rem & 1023;
        float v;
        if (r < 24) v = Whh0[phys_row(cta, r) * HH + k];
        else        v = Wout[(cta * 2 + (r - 24)) * HH + k];
        g_WP1[idx] = __float2half_rn(v);
        return;
    }
    idx -= N1;
    if (idx < N2) {
        int cta = idx / 6144, rem = idx % 6144;
        int r = rem >> 8, k = rem & 255;
        g_WP2[idx] = __float2half_rn(Wih0[phys_row(cta, r) * DD + k]);
        return;
    }
    idx -= N2;
    if (idx < N3) {
        int cta = idx / 24576, rem = idx % 24576;
        int r = rem >> 10, k = rem & 1023;
        int p = phys_row(cta, r);
        g_WP3[idx] = __float2half_rn(Wih1[p * HH + k] + Whh1[p * HH + k]);
        return;
    }
    idx -= N3;
    if (idx < NBv) {
        int p = phys_row(idx / 24, idx % 24);
        g_B0[idx] = bih0[p] + bhh0[p];
        g_B1[idx] = bih1[p] + bhh1[p];
        return;
    }
    idx -= NBv;
    if (idx < NHh) {
        g_h[idx] = __float2half_rn(0.0f);
        if (idx == 0) g_barcnt = 0;
    }
}

// ------------------------- pipeline pieces -------------------------
template<int R>
__device__ __forceinline__ void load_stage(unsigned smb, int st,
        const __half* __restrict__ A, int ldA,
        const __half* __restrict__ W, int ldW,
        int khalf, int kbase, int tid) {
    // A: 4 kw x 64 rows x 8 segs(16B) = 2048 slots
    #pragma unroll
    for (int i = 0; i < 4; i++) {
        int u = tid + i * NTHR;
        int kwv = u >> 9, v = u & 511;
        int row = v >> 3, seg = (v & 7) << 3;   // seg in halves
        cpa16(smb + 2u * As_idx(st, kwv, row, seg),
              A + row * ldA + kwv * khalf + kbase + seg);
    }
    // W: 4 kw x 32 rows x 8 segs = 1024 slots (guard row<R)
    #pragma unroll
    for (int i = 0; i < 2; i++) {
        int u = tid + i * NTHR;
        int kwv = u >> 8, v = u & 255;
        int row = v >> 3, seg = (v & 7) << 3;
        if (row < R)
            cpa16(smb + 2u * Ws_idx(st, kwv, row, seg),
                  W + row * ldW + kwv * khalf + kbase + seg);
    }
    cpcommit();
}

// ldmatrix-based fragment compute: always 4 n-blocks (pads finite/zero)
__device__ __forceinline__ void compute_chunk(unsigned smb, int st,
        int kw, int m0, int lane, float acc[4][4]) {
    const unsigned abase = smb + 2u * As_idx(st, kw, m0 + (lane & 15), (lane >> 4) << 3);
    const unsigned bbase = smb + 2u * Ws_idx(st, kw,
                                (lane & 7) + ((lane & 16) ? 8 : 0),
                                (lane & 8) ? 8 : 0);
    #pragma unroll
    for (int s = 0; s < 4; s++) {
        unsigned aa[4];
        asm volatile("ldmatrix.sync.aligned.m8n8.x4.shared.b16 {%0,%1,%2,%3}, [%4];"
            : "=r"(aa[0]), "=r"(aa[1]), "=r"(aa[2]), "=r"(aa[3])
            : "r"(abase + s * 32));
        #pragma unroll
        for (int bp = 0; bp < 2; bp++) {
            unsigned bb[4];
            asm volatile("ldmatrix.sync.aligned.m8n8.x4.shared.b16 {%0,%1,%2,%3}, [%4];"
                : "=r"(bb[0]), "=r"(bb[1]), "=r"(bb[2]), "=r"(bb[3])
                : "r"(bbase + bp * (16 * SROW_H * 2) + s * 32));
            mma_f16(acc[bp * 2],     aa, bb);
            mma_f16(acc[bp * 2 + 1], aa, bb + 2);
        }
    }
}

// 3-stage ring, depth-2 prefetch, ONE sync per chunk.
template<int R>
__device__ __forceinline__ void run_phase(unsigned smb,
        const __half* A, int ldA, const __half* W, int ldW, int khalf,
        float acc[4][4], int tid, int kw, int m0, int lane) {
    const int nit = khalf / CHH;
    load_stage<R>(smb, 0, A, ldA, W, ldW, khalf, 0, tid);
    if (nit > 1) load_stage<R>(smb, 1, A, ldA, W, ldW, khalf, CHH, tid);
    int st = 0;
    for (int it = 0; it < nit; it++) {
        if (it + 1 < nit)
            asm volatile("cp.async.wait_group 1;" ::: "memory");
        else
            asm volatile("cp.async.wait_group 0;" ::: "memory");
        __syncthreads();
        if (it + 2 < nit) {
            int slot = st + 2; if (slot >= 3) slot -= 3;
            load_stage<R>(smb, slot, A, ldA, W, ldW, khalf, (it + 2) * CHH, tid);
        }
        compute_chunk(smb, st, kw, m0, lane, acc);
        if (++st == 3) st = 0;
    }
}

// 4-way kw reduce through smem scratch, one sync
__device__ __forceinline__ void reduce_blocks(float* red, float acc[4][4],
        int kw, int mw, int lane, int b0, int b1) {
    if (kw > 0) {
        float* p = red + (((kw - 1) * 4 + mw) * 32 + lane) * 16;
        for (int blk = b0; blk <= b1; blk++)
            *(float4*)&p[blk * 4] = *(const float4*)acc[blk];
    }
    __syncthreads();
    if (kw == 0) {
        #pragma unroll
        for (int g = 0; g < 3; g++) {
            const float* p = red + ((g * 4 + mw) * 32 + lane) * 16;
            for (int blk = b0; blk <= b1; blk++) {
                float4 v = *(const float4*)&p[blk * 4];
                acc[blk][0] += v.x; acc[blk][1] += v.y;
                acc[blk][2] += v.z; acc[blk][3] += v.w;
            }
        }
    }
}

// proven atomic barrier (R7/R10)
__device__ __forceinline__ void gridbar(unsigned* barno) {
    __syncthreads();
    (*barno)++;
    if (threadIdx.x == 0) {
        __threadfence();
        atomicAdd(&g_barcnt, 1u);
        unsigned target = (*barno) * NCTA, v;
        do {
            asm volatile("ld.acquire.gpu.global.u32 %0, [%1];" : "=r"(v) : "l"(&g_barcnt) : "memory");
        } while (v < target);
    }
    __syncthreads();
}

// ------------------------- persistent kernel -------------------------
__global__ void __launch_bounds__(NTHR, 1) rnn_persist(
        const float* __restrict__ X, const float* __restrict__ Mm,
        const float* __restrict__ bout, float* __restrict__ out) {
    extern __shared__ char smraw[];
    __half* sm = (__half*)smraw;
    float* red = (float*)(smraw + RED_BYTE_OFF);
    unsigned smb = (unsigned)__cvta_generic_to_shared(smraw);
    const int cta = blockIdx.x, tid = threadIdx.x;
    const int warp = tid >> 5, lane = tid & 31;
    const int mw = warp & 3, kw = warp >> 2;     // mw 0..3, kw 0..3
    const int m0 = mw << 4, r = lane >> 2, c = lane & 3;
    const __half* WP1 = g_WP1 + cta * 26 * HH;
    const __half* WP2 = g_WP2 + cta * 24 * DD;
    const __half* WP3 = g_WP3 + cta * 24 * HH;
    const float* B0p = g_B0 + cta * 24;
    const float* B1p = g_B1 + cta * 24;
    const int u0 = cta * 8, d0 = cta * 2;
    unsigned barno = 0;
    float acc[4][4];

    // zero the W pad rows (26..31) of every stage/kw once (never overwritten)
    for (int i = tid; i < 3 * NKW * 6 * SROW_H; i += NTHR) {
        int st = i / (NKW * 6 * SROW_H), rem = i % (NKW * 6 * SROW_H);
        int kwz = rem / (6 * SROW_H), rem2 = rem % (6 * SROW_H);
        sm[Ws_idx(st, kwz, 26 + rem2 / SROW_H, rem2 % SROW_H)] = __float2half_rn(0.0f);
    }
    __syncthreads();

    for (int t = 0;; t++) {
        if (t == TT) {   // h_final -> out tail (fp32 copy)
            for (int i = tid; i < 512; i += NTHR)
                out[BB * TT * DD + cta * 512 + i] = g_hf[cta * 512 + i];
        }
        // ---- P1: [gates0-h (24) | est (2, block 3)] = h @ WP1^T (k=1024) ----
        // blocks 0-2 stay per-kw partials (carried into P2, reduced once there);
        // ONLY block 3 (est) is reduced here.
        #pragma unroll
        for (int blk = 0; blk < 4; blk++)
            #pragma unroll
            for (int q = 0; q < 4; q++) acc[blk][q] = 0.0f;
        run_phase<26>(smb, g_h, HH, WP1, HH, 256, acc, tid, kw, m0, lane);
        reduce_blocks(red, acc, kw, mw, lane, 3, 3);
        if (kw == 0 && c == 0) {   // est epilogue: cols 0,1 of block 3
            #pragma unroll
            for (int half = 0; half < 2; half++) {
                int b = m0 + r + half * 8;
                float ev[2];
                #pragma unroll
                for (int j = 0; j < 2; j++) {
                    int d = d0 + j;
                    float e = acc[3][half * 2 + j] + bout[d];
                    if (t > 0) out[(b * TT + (t - 1)) * DD + d] = e;
                    if (t < TT) {
                        int xi = (b * TT + t) * DD + d;
                        float m = Mm[xi];
                        ev[j] = m * X[xi] + (1.0f - m) * e;
                    }
                }
                if (t < TT)
                    *(__half2*)&g_imp[b * DD + d0] = __floats2half2_rn(ev[0], ev[1]);
            }
        }
        if (t == TT) break;
        gridbar(&barno);

        // ---- P2: gates0 += imp @ WP2^T (k=256), act0 -> h0 ----
        run_phase<24>(smb, g_imp, DD, WP2, DD, 64, acc, tid, kw, m0, lane);
        reduce_blocks(red, acc, kw, mw, lane, 0, 2);
        if (kw == 0) {
            #pragma unroll
            for (int half = 0; half < 2; half++) {
                int b = m0 + r + half * 8;
                float hv[2];
                #pragma unroll
                for (int j = 0; j < 2; j++) {
                    int col = 2 * c + j;
                    float gi = acc[0][half * 2 + j] + B0p[col];
                    float gg = acc[1][half * 2 + j] + B0p[8 + col];
                    float go = acc[2][half * 2 + j] + B0p[16 + col];
                    float si = 1.0f / (1.0f + expf(-gi));
                    float so = 1.0f / (1.0f + expf(-go));
                    hv[j] = so * tanhf(si * tanhf(gg));
                }
                *(__half2*)&g_h0[b * HH + u0 + 2 * c] = __floats2half2_rn(hv[0], hv[1]);
            }
        }
        gridbar(&barno);

        // ---- P3: gates1 = h0 @ WP3^T (k=1024), act1 -> h ----
        #pragma unroll
        for (int blk = 0; blk < 4; blk++)
            #pragma unroll
            for (int q = 0; q < 4; q++) acc[blk][q] = 0.0f;
        run_phase<24>(smb, g_h0, HH, WP3, HH, 256, acc, tid, kw, m0, lane);
        reduce_blocks(red, acc, kw, mw, lane, 0, 2);
        if (kw == 0) {
            #pragma unroll
            for (int half = 0; half < 2; half++) {
                int b = m0 + r + half * 8;
                float hv[2];
                #pragma unroll
                for (int j = 0; j < 2; j++) {
                    int col = 2 * c + j;
                    float gi = acc[0][half * 2 + j] + B1p[col];
                    float gg = acc[1][half * 2 + j] + B1p[8 + col];
                    float go = acc[2][half * 2 + j] + B1p[16 + col];
                    float si = 1.0f / (1.0f + expf(-gi));
                    float so = 1.0f / (1.0f + expf(-go));
                    hv[j] = so * tanhf(si * tanhf(gg));
                }
                *(__half2*)&g_h[b * HH + u0 + 2 * c] = __floats2half2_rn(hv[0], hv[1]);
                if (t == TT - 1)
                    *(float2*)&g_hf[b * HH + u0 + 2 * c] = make_float2(hv[0], hv[1]);
            }
        }
        gridbar(&barno);
    }
}

// ------------------------------- launch --------------------------------
extern "C" void kernel_launch(void* const* d_in, const int* in_sizes, int n_in,
                              void* d_out, int out_size) {
    const float* X    = (const float*)d_in[0];
    const float* Mm   = (const float*)d_in[1];
    const float* Wih0 = (const float*)d_in[2];
    const float* Whh0 = (const float*)d_in[3];
    const float* bih0 = (const float*)d_in[4];
    const float* bhh0 = (const float*)d_in[5];
    const float* Wih1 = (const float*)d_in[6];
    const float* Whh1 = (const float*)d_in[7];
    const float* bih1 = (const float*)d_in[8];
    const float* bhh1 = (const float*)d_in[9];
    const float* Wout = (const float*)d_in[10];
    const float* bout = (const float*)d_in[11];
    float* out = (float*)d_out;

    cudaFuncSetAttribute(rnn_persist, cudaFuncAttributeMaxDynamicSharedMemorySize,
                         SMEM_BYTES);

    pack_all<<<(PACK_TOT + 255) / 256, 256>>>(Wih0, Whh0, bih0, bhh0,
                                              Wih1, Whh1, bih1, bhh1, Wout);
    rnn_persist<<<NCTA, NTHR, SMEM_BYTES>>>(X, Mm, bout, out);
}

// round 14
// speedup vs baseline: 1.0978x; 1.0978x over previous
#include <cuda_runtime.h>
#include <cuda_fp16.h>
#include <math.h>

#define BB 64
#define TT 128
#define DD 256
#define HH 1024
#define NCTA 128
#define NTHR 256
#define CHH 128                  // k-chunk (halves) per kw per stage
#define SROW_H 136               // smem row stride in halves (272B)
#define STAGE_H (2*96*SROW_H)    // 26112 halves per stage
#define RED_BYTE_OFF (3*STAGE_H*2)          // 156672 B
#define SMEM_BYTES (RED_BYTE_OFF + 2048*4)  // + 8KB fp32 reduce scratch

// ------------------------- device globals -------------------------
__device__ __half g_WP1[NCTA*26*HH];  // per-CTA: 24 Whh0 i/g/o rows + 2 Wout rows
__device__ __half g_WP2[NCTA*24*DD];  // per-CTA Wih0 i/g/o rows
__device__ __half g_WP3[NCTA*24*HH];  // per-CTA (Wih1+Whh1) i/g/o rows
__device__ float  g_B0[NCTA*24];
__device__ float  g_B1[NCTA*24];
__device__ __half g_h[BB*HH];
__device__ __half g_h0[BB*HH];
__device__ __half g_imp[BB*DD];
__device__ float  g_hf[BB*HH];        // fp32 h_final (written at t==TT-1)
__device__ unsigned g_bar8[8*64];     // 8 arrival counters, 256B apart (distinct LTS)

// ------------------------- helpers -------------------------
__device__ __forceinline__ void mma_f16(float* d, const unsigned* a, const unsigned* b) {
    asm volatile(
        "mma.sync.aligned.m16n8k16.row.col.f32.f16.f16.f32 "
        "{%0,%1,%2,%3},{%4,%5,%6,%7},{%8,%9},{%0,%1,%2,%3};"
        : "+f"(d[0]), "+f"(d[1]), "+f"(d[2]), "+f"(d[3])
        : "r"(a[0]), "r"(a[1]), "r"(a[2]), "r"(a[3]), "r"(b[0]), "r"(b[1]));
}
__device__ __forceinline__ void cpa16(unsigned s, const void* g) {
    asm volatile("cp.async.cg.shared.global [%0], [%1], 16;" :: "r"(s), "l"(g));
}
__device__ __forceinline__ void cpcommit() { asm volatile("cp.async.commit_group;"); }

__device__ __forceinline__ int As_idx(int st, int kw, int row, int k) {   // halves
    return st * STAGE_H + (kw * 96 + row) * SROW_H + k;
}
__device__ __forceinline__ int Ws_idx(int st, int kw, int row, int k) {
    return st * STAGE_H + (kw * 96 + 64 + row) * SROW_H + k;
}

// ------------------------- pack kernel -------------------------
__device__ __forceinline__ int phys_row(int cta, int r) {  // r in [0,24)
    int u = cta * 8 + (r & 7);
    int g = r >> 3;
    return u + (g == 0 ? 0 : (g == 1 ? 2048 : 3072));
}
#define N1 (NCTA*26*HH)
#define N2 (NCTA*24*DD)
#define N3 (NCTA*24*HH)
#define NBv (NCTA*24)
#define NHh (BB*HH)
#define NBar (8*64)
#define PACK_TOT (N1+N2+N3+NBv+NHh+NBar)

__global__ void pack_all(const float* __restrict__ Wih0, const float* __restrict__ Whh0,
                         const float* __restrict__ bih0, const float* __restrict__ bhh0,
                         const float* __restrict__ Wih1, const float* __restrict__ Whh1,
                         const float* __restrict__ bih1, const float* __restrict__ bhh1,
                         const float* __restrict__ Wout) {
    int idx = blockIdx.x * 256 + threadIdx.x;
    if (idx < N1) {
        int cta = idx / 26624, rem = idx % 26624;
        int r = rem >> 10, k = rem & 1023;
        float v;
        if (r < 24) v = Whh0[phys_row(cta, r) * HH + k];
        else        v = Wout[(cta * 2 + (r - 24)) * HH + k];
        g_WP1[idx] = __float2half_rn(v);
        return;
    }
    idx -= N1;
    if (idx < N2) {
        int cta = idx / 6144, rem = idx % 6144;
        int r = rem >> 8, k = rem & 255;
        g_WP2[idx] = __float2half_rn(Wih0[phys_row(cta, r) * DD + k]);
        return;
    }
    idx -= N2;
    if (idx < N3) {
        int cta = idx / 24576, rem = idx % 24576;
        int r = rem >> 10, k = rem & 1023;
        int p = phys_row(cta, r);
        g_WP3[idx] = __float2half_rn(Wih1[p * HH + k] + Whh1[p * HH + k]);
        return;
    }
    idx -= N3;
    if (idx < NBv) {
        int p = phys_row(idx / 24, idx % 24);
        g_B0[idx] = bih0[p] + bhh0[p];
        g_B1[idx] = bih1[p] + bhh1[p];
        return;
    }
    idx -= NBv;
    if (idx < NHh) {
        g_h[idx] = __float2half_rn(0.0f);
        return;
    }
    idx -= NHh;
    if (idx < NBar) g_bar8[idx] = 0;
}

// ------------------------- pipeline pieces -------------------------
template<int R>
__device__ __forceinline__ void load_stage(unsigned smb, int st,
        const __half* __restrict__ A, int ldA,
        const __half* __restrict__ W, int ldW,
        int khalf, int kbase, int tid) {
    // A: 2 kw x 64 rows x 16 segs(16B) = 2048 slots
    #pragma unroll
    for (int i = 0; i < 8; i++) {
        int u = tid + i * NTHR;
        int kw = u >> 10, v = u & 1023;
        int row = v >> 4, seg = (v & 15) << 3;   // seg in halves
        cpa16(smb + 2u * As_idx(st, kw, row, seg),
              A + row * ldA + kw * khalf + kbase + seg);
    }
    // W: 2 kw x 32 rows x 16 segs = 1024 slots (guard row<R)
    #pragma unroll
    for (int i = 0; i < 4; i++) {
        int u = tid + i * NTHR;
        int kw = u >> 9, v = u & 511;
        int row = v >> 4, seg = (v & 15) << 3;
        if (row < R)
            cpa16(smb + 2u * Ws_idx(st, kw, row, seg),
                  W + row * ldW + kw * khalf + kbase + seg);
    }
    cpcommit();
}

// ldmatrix-based fragment compute: always 4 n-blocks (pads finite/zero)
__device__ __forceinline__ void compute_chunk(unsigned smb, int st,
        int kw, int m0, int lane, float acc[4][4]) {
    const unsigned abase = smb + 2u * As_idx(st, kw, m0 + (lane & 15), (lane >> 4) << 3);
    const unsigned bbase = smb + 2u * Ws_idx(st, kw,
                                (lane & 7) + ((lane & 16) ? 8 : 0),
                                (lane & 8) ? 8 : 0);
    #pragma unroll
    for (int s = 0; s < 8; s++) {
        unsigned aa[4];
        asm volatile("ldmatrix.sync.aligned.m8n8.x4.shared.b16 {%0,%1,%2,%3}, [%4];"
            : "=r"(aa[0]), "=r"(aa[1]), "=r"(aa[2]), "=r"(aa[3])
            : "r"(abase + s * 32));
        #pragma unroll
        for (int bp = 0; bp < 2; bp++) {
            unsigned bb[4];
            asm volatile("ldmatrix.sync.aligned.m8n8.x4.shared.b16 {%0,%1,%2,%3}, [%4];"
                : "=r"(bb[0]), "=r"(bb[1]), "=r"(bb[2]), "=r"(bb[3])
                : "r"(bbase + bp * (16 * SROW_H * 2) + s * 32));
            mma_f16(acc[bp * 2],     aa, bb);
            mma_f16(acc[bp * 2 + 1], aa, bb + 2);
        }
    }
}

// 3-stage ring, depth-2 prefetch, ONE sync per chunk.
template<int R>
__device__ __forceinline__ void run_phase(unsigned smb,
        const __half* A, int ldA, const __half* W, int ldW, int khalf,
        float acc[4][4], int tid, int kw, int m0, int lane) {
    const int nit = khalf / CHH;
    load_stage<R>(smb, 0, A, ldA, W, ldW, khalf, 0, tid);
    if (nit > 1) load_stage<R>(smb, 1, A, ldA, W, ldW, khalf, CHH, tid);
    int st = 0;
    for (int it = 0; it < nit; it++) {
        if (it + 1 < nit)
            asm volatile("cp.async.wait_group 1;" ::: "memory");
        else
            asm volatile("cp.async.wait_group 0;" ::: "memory");
        __syncthreads();
        if (it + 2 < nit) {
            int slot = st + 2; if (slot >= 3) slot -= 3;
            load_stage<R>(smb, slot, A, ldA, W, ldW, khalf, (it + 2) * CHH, tid);
        }
        compute_chunk(smb, st, kw, m0, lane, acc);
        if (++st == 3) st = 0;
    }
}

__device__ __forceinline__ void reduce_blocks(float* red, float acc[4][4],
        int kw, int mw, int lane, int b0, int b1) {
    if (kw == 1)
        for (int blk = b0; blk <= b1; blk++)
            #pragma unroll
            for (int q = 0; q < 4; q++)
                red[((mw * 4 + blk) * 32 + lane) * 4 + q] = acc[blk][q];
    __syncthreads();
    if (kw == 0)
        for (int blk = b0; blk <= b1; blk++)
            #pragma unroll
            for (int q = 0; q < 4; q++)
                acc[blk][q] += red[((mw * 4 + blk) * 32 + lane) * 4 + q];
}

// distributed-arrival barrier: 8 counters (256B apart -> distinct LTS slices),
// CTA c arrives on counter c&7 (16 arrivals each); threads tid<8 each poll one
// counter (128 pollers/line = R7-proven contention level).
__device__ __forceinline__ void gridbar(unsigned* barno, int cta, int tid) {
    __syncthreads();
    (*barno)++;
    const unsigned target = 16u * (*barno);
    if (tid == 0) {
        __threadfence();
        atomicAdd(&g_bar8[(cta & 7) * 64], 1u);
    }
    if (tid < 8) {
        const unsigned* p = &g_bar8[tid * 64];
        unsigned v;
        do {
            asm volatile("ld.acquire.gpu.global.u32 %0, [%1];" : "=r"(v) : "l"(p) : "memory");
        } while (v < target);
    }
    __syncthreads();
}

// ------------------------- persistent kernel -------------------------
__global__ void __launch_bounds__(NTHR, 1) rnn_persist(
        const float* __restrict__ X, const float* __restrict__ Mm,
        const float* __restrict__ bout, float* __restrict__ out) {
    extern __shared__ char smraw[];
    __half* sm = (__half*)smraw;
    float* red = (float*)(smraw + RED_BYTE_OFF);
    unsigned smb = (unsigned)__cvta_generic_to_shared(smraw);
    const int cta = blockIdx.x, tid = threadIdx.x;
    const int warp = tid >> 5, lane = tid & 31;
    const int mw = warp & 3, kw = warp >> 2;
    const int m0 = mw << 4, r = lane >> 2, c = lane & 3;
    const __half* WP1 = g_WP1 + cta * 26 * HH;
    const __half* WP2 = g_WP2 + cta * 24 * DD;
    const __half* WP3 = g_WP3 + cta * 24 * HH;
    const float* B0p = g_B0 + cta * 24;
    const float* B1p = g_B1 + cta * 24;
    const int u0 = cta * 8, d0 = cta * 2;
    unsigned barno = 0;
    float acc[4][4];

    // zero the W pad rows (26..31) of every stage/kw once (never overwritten)
    for (int i = tid; i < 3 * 2 * 6 * SROW_H; i += NTHR) {
        int st = i / (2 * 6 * SROW_H), rem = i % (2 * 6 * SROW_H);
        int kwz = rem / (6 * SROW_H), rem2 = rem % (6 * SROW_H);
        sm[Ws_idx(st, kwz, 26 + rem2 / SROW_H, rem2 % SROW_H)] = __float2half_rn(0.0f);
    }
    __syncthreads();

    for (int t = 0;; t++) {
        if (t == TT) {   // h_final -> out tail (fp32 copy)
            for (int i = tid; i < 512; i += NTHR)
                out[BB * TT * DD + cta * 512 + i] = g_hf[cta * 512 + i];
        }
        // ---- P1: [gates0-h (24) | est (2, block 3)] = h @ WP1^T (k=1024) ----
        // blocks 0-2 stay per-kw partials (reduced once after P2); only block 3 here.
        #pragma unroll
        for (int blk = 0; blk < 4; blk++)
            #pragma unroll
            for (int q = 0; q < 4; q++) acc[blk][q] = 0.0f;
        run_phase<26>(smb, g_h, HH, WP1, HH, 512, acc, tid, kw, m0, lane);
        reduce_blocks(red, acc, kw, mw, lane, 3, 3);
        if (kw == 0 && c == 0) {   // est epilogue: cols 0,1 of block 3
            #pragma unroll
            for (int half = 0; half < 2; half++) {
                int b = m0 + r + half * 8;
                float ev[2];
                #pragma unroll
                for (int j = 0; j < 2; j++) {
                    int d = d0 + j;
                    float e = acc[3][half * 2 + j] + bout[d];
                    if (t > 0) out[(b * TT + (t - 1)) * DD + d] = e;
                    if (t < TT) {
                        int xi = (b * TT + t) * DD + d;
                        float m = Mm[xi];
                        ev[j] = m * X[xi] + (1.0f - m) * e;
                    }
                }
                if (t < TT)
                    *(__half2*)&g_imp[b * DD + d0] = __floats2half2_rn(ev[0], ev[1]);
            }
        }
        if (t == TT) break;
        gridbar(&barno, cta, tid);

        // ---- P2: gates0 += imp @ WP2^T (k=256), act0 -> h0 ----
        run_phase<24>(smb, g_imp, DD, WP2, DD, 128, acc, tid, kw, m0, lane);
        reduce_blocks(red, acc, kw, mw, lane, 0, 2);
        if (kw == 0) {
            #pragma unroll
            for (int half = 0; half < 2; half++) {
                int b = m0 + r + half * 8;
                float hv[2];
                #pragma unroll
                for (int j = 0; j < 2; j++) {
                    int col = 2 * c + j;
                    float gi = acc[0][half * 2 + j] + B0p[col];
                    float gg = acc[1][half * 2 + j] + B0p[8 + col];
                    float go = acc[2][half * 2 + j] + B0p[16 + col];
                    float si = 1.0f / (1.0f + expf(-gi));
                    float so = 1.0f / (1.0f + expf(-go));
                    hv[j] = so * tanhf(si * tanhf(gg));
                }
                *(__half2*)&g_h0[b * HH + u0 + 2 * c] = __floats2half2_rn(hv[0], hv[1]);
            }
        }
        gridbar(&barno, cta, tid);

        // ---- P3: gates1 = h0 @ WP3^T (k=1024), act1 -> h ----
        #pragma unroll
        for (int blk = 0; blk < 4; blk++)
            #pragma unroll
            for (int q = 0; q < 4; q++) acc[blk][q] = 0.0f;
        run_phase<24>(smb, g_h0, HH, WP3, HH, 512, acc, tid, kw, m0, lane);
        reduce_blocks(red, acc, kw, mw, lane, 0, 2);
        if (kw == 0) {
            #pragma unroll
            for (int half = 0; half < 2; half++) {
                int b = m0 + r + half * 8;
                float hv[2];
                #pragma unroll
                for (int j = 0; j < 2; j++) {
                    int col = 2 * c + j;
                    float gi = acc[0][half * 2 + j] + B1p[col];
                    float gg = acc[1][half * 2 + j] + B1p[8 + col];
                    float go = acc[2][half * 2 + j] + B1p[16 + col];
                    float si = 1.0f / (1.0f + expf(-gi));
                    float so = 1.0f / (1.0f + expf(-go));
                    hv[j] = so * tanhf(si * tanhf(gg));
                }
                *(__half2*)&g_h[b * HH + u0 + 2 * c] = __floats2half2_rn(hv[0], hv[1]);
                if (t == TT - 1)
                    *(float2*)&g_hf[b * HH + u0 + 2 * c] = make_float2(hv[0], hv[1]);
            }
        }
        gridbar(&barno, cta, tid);
    }
}

// ------------------------------- launch --------------------------------
extern "C" void kernel_launch(void* const* d_in, const int* in_sizes, int n_in,
                              void* d_out, int out_size) {
    const float* X    = (const float*)d_in[0];
    const float* Mm   = (const float*)d_in[1];
    const float* Wih0 = (const float*)d_in[2];
    const float* Whh0 = (const float*)d_in[3];
    const float* bih0 = (const float*)d_in[4];
    const float* bhh0 = (const float*)d_in[5];
    const float* Wih1 = (const float*)d_in[6];
    const float* Whh1 = (const float*)d_in[7];
    const float* bih1 = (const float*)d_in[8];
    const float* bhh1 = (const float*)d_in[9];
    const float* Wout = (const float*)d_in[10];
    const float* bout = (const float*)d_in[11];
    float* out = (float*)d_out;

    cudaFuncSetAttribute(rnn_persist, cudaFuncAttributeMaxDynamicSharedMemorySize,
                         SMEM_BYTES);

    pack_all<<<(PACK_TOT + 255) / 256, 256>>>(Wih0, Whh0, bih0, bhh0,
                                              Wih1, Whh1, bih1, bhh1, Wout);
    rnn_persist<<<NCTA, NTHR, SMEM_BYTES>>>(X, Mm, bout, out);
}

// round 15
// speedup vs baseline: 1.1698x; 1.0655x over previous
#include <cuda_runtime.h>
#include <cuda_fp16.h>
#include <math.h>

#define BB 64
#define TT 128
#define DD 256
#define HH 1024
#define NCTA 128
#define NTHR 256
#define CHH 128                  // k-chunk (halves) per kw per stage
#define SROW_H 136               // smem row stride in halves (272B)
#define STAGE_H (2*96*SROW_H)    // 26112 halves per stage
#define RED_BYTE_OFF (3*STAGE_H*2)          // 156672 B
#define SMEM_BYTES (RED_BYTE_OFF + 2048*4)  // + 8KB fp32 reduce scratch

// ------------------------- device globals -------------------------
__device__ __half g_WP1[NCTA*26*HH];  // per-CTA: 24 Whh0 i/g/o rows + 2 Wout rows
__device__ __half g_WP2[NCTA*24*DD];  // per-CTA Wih0 i/g/o rows
__device__ __half g_WP3[NCTA*24*HH];  // per-CTA (Wih1+Whh1) i/g/o rows
__device__ float  g_B0[NCTA*24];
__device__ float  g_B1[NCTA*24];
__device__ __half g_h[BB*HH];
__device__ __half g_h0[BB*HH];
__device__ __half g_imp[BB*DD];
__device__ float  g_hf[BB*HH];        // fp32 h_final (written at t==TT-1)
__device__ unsigned g_bar8[8*64];     // 8 arrival counters, 256B apart (distinct LTS)

// ------------------------- helpers -------------------------
__device__ __forceinline__ void mma_f16(float* d, const unsigned* a, const unsigned* b) {
    asm volatile(
        "mma.sync.aligned.m16n8k16.row.col.f32.f16.f16.f32 "
        "{%0,%1,%2,%3},{%4,%5,%6,%7},{%8,%9},{%0,%1,%2,%3};"
        : "+f"(d[0]), "+f"(d[1]), "+f"(d[2]), "+f"(d[3])
        : "r"(a[0]), "r"(a[1]), "r"(a[2]), "r"(a[3]), "r"(b[0]), "r"(b[1]));
}
__device__ __forceinline__ void cpa16(unsigned s, const void* g) {
    asm volatile("cp.async.cg.shared.global [%0], [%1], 16;" :: "r"(s), "l"(g));
}
__device__ __forceinline__ void cpcommit() { asm volatile("cp.async.commit_group;"); }

__device__ __forceinline__ int As_idx(int st, int kw, int row, int k) {   // halves
    return st * STAGE_H + (kw * 96 + row) * SROW_H + k;
}
__device__ __forceinline__ int Ws_idx(int st, int kw, int row, int k) {
    return st * STAGE_H + (kw * 96 + 64 + row) * SROW_H + k;
}

// ------------------------- pack kernel -------------------------
__device__ __forceinline__ int phys_row(int cta, int r) {  // r in [0,24)
    int u = cta * 8 + (r & 7);
    int g = r >> 3;
    return u + (g == 0 ? 0 : (g == 1 ? 2048 : 3072));
}
#define N1 (NCTA*26*HH)
#define N2 (NCTA*24*DD)
#define N3 (NCTA*24*HH)
#define NBv (NCTA*24)
#define NHh (BB*HH)
#define NBar (8*64)
#define PACK_TOT (N1+N2+N3+NBv+NHh+NBar)

__global__ void pack_all(const float* __restrict__ Wih0, const float* __restrict__ Whh0,
                         const float* __restrict__ bih0, const float* __restrict__ bhh0,
                         const float* __restrict__ Wih1, const float* __restrict__ Whh1,
                         const float* __restrict__ bih1, const float* __restrict__ bhh1,
                         const float* __restrict__ Wout) {
    int idx = blockIdx.x * 256 + threadIdx.x;
    if (idx < N1) {
        int cta = idx / 26624, rem = idx % 26624;
        int r = rem >> 10, k = rem & 1023;
        float v;
        if (r < 24) v = Whh0[phys_row(cta, r) * HH + k];
        else        v = Wout[(cta * 2 + (r - 24)) * HH + k];
        g_WP1[idx] = __float2half_rn(v);
        return;
    }
    idx -= N1;
    if (idx < N2) {
        int cta = idx / 6144, rem = idx % 6144;
        int r = rem >> 8, k = rem & 255;
        g_WP2[idx] = __float2half_rn(Wih0[phys_row(cta, r) * DD + k]);
        return;
    }
    idx -= N2;
    if (idx < N3) {
        int cta = idx / 24576, rem = idx % 24576;
        int r = rem >> 10, k = rem & 1023;
        int p = phys_row(cta, r);
        g_WP3[idx] = __float2half_rn(Wih1[p * HH + k] + Whh1[p * HH + k]);
        return;
    }
    idx -= N3;
    if (idx < NBv) {
        int p = phys_row(idx / 24, idx % 24);
        g_B0[idx] = bih0[p] + bhh0[p];
        g_B1[idx] = bih1[p] + bhh1[p];
        return;
    }
    idx -= NBv;
    if (idx < NHh) {
        g_h[idx] = __float2half_rn(0.0f);
        return;
    }
    idx -= NHh;
    if (idx < NBar) g_bar8[idx] = 0;
}

// ------------------------- pipeline pieces -------------------------
template<int R>
__device__ __forceinline__ void load_stage(unsigned smb, int st,
        const __half* __restrict__ A, int ldA,
        const __half* __restrict__ W, int ldW,
        int khalf, int kbase, int tid) {
    // A: 2 kw x 64 rows x 16 segs(16B) = 2048 slots
    #pragma unroll
    for (int i = 0; i < 8; i++) {
        int u = tid + i * NTHR;
        int kw = u >> 10, v = u & 1023;
        int row = v >> 4, seg = (v & 15) << 3;   // seg in halves
        cpa16(smb + 2u * As_idx(st, kw, row, seg),
              A + row * ldA + kw * khalf + kbase + seg);
    }
    // W: 2 kw x 32 rows x 16 segs = 1024 slots (guard row<R)
    #pragma unroll
    for (int i = 0; i < 4; i++) {
        int u = tid + i * NTHR;
        int kw = u >> 9, v = u & 511;
        int row = v >> 4, seg = (v & 15) << 3;
        if (row < R)
            cpa16(smb + 2u * Ws_idx(st, kw, row, seg),
                  W + row * ldW + kw * khalf + kbase + seg);
    }
    cpcommit();
}

// ldmatrix-based fragment compute; NBLK=4 (blocks 0-3) or 3 (blocks 0-2)
template<int NBLK>
__device__ __forceinline__ void compute_chunk(unsigned smb, int st,
        int kw, int m0, int lane, float acc[4][4]) {
    const unsigned abase = smb + 2u * As_idx(st, kw, m0 + (lane & 15), (lane >> 4) << 3);
    const unsigned bbase4 = smb + 2u * Ws_idx(st, kw,
                                (lane & 7) + ((lane & 16) ? 8 : 0),
                                (lane & 8) ? 8 : 0);
    const unsigned bbase2 = smb + 2u * Ws_idx(st, kw,
                                16 + (lane & 7),
                                (lane & 8) ? 8 : 0);
    #pragma unroll
    for (int s = 0; s < 8; s++) {
        unsigned aa[4];
        asm volatile("ldmatrix.sync.aligned.m8n8.x4.shared.b16 {%0,%1,%2,%3}, [%4];"
            : "=r"(aa[0]), "=r"(aa[1]), "=r"(aa[2]), "=r"(aa[3])
            : "r"(abase + s * 32));
        // blocks 0,1
        {
            unsigned bb[4];
            asm volatile("ldmatrix.sync.aligned.m8n8.x4.shared.b16 {%0,%1,%2,%3}, [%4];"
                : "=r"(bb[0]), "=r"(bb[1]), "=r"(bb[2]), "=r"(bb[3])
                : "r"(bbase4 + s * 32));
            mma_f16(acc[0], aa, bb);
            mma_f16(acc[1], aa, bb + 2);
        }
        if (NBLK == 4) {          // blocks 2,3
            unsigned bb[4];
            asm volatile("ldmatrix.sync.aligned.m8n8.x4.shared.b16 {%0,%1,%2,%3}, [%4];"
                : "=r"(bb[0]), "=r"(bb[1]), "=r"(bb[2]), "=r"(bb[3])
                : "r"(bbase4 + (16 * SROW_H * 2) + s * 32));
            mma_f16(acc[2], aa, bb);
            mma_f16(acc[3], aa, bb + 2);
        } else {                  // block 2 only
            unsigned bb[2];
            asm volatile("ldmatrix.sync.aligned.m8n8.x2.shared.b16 {%0,%1}, [%2];"
                : "=r"(bb[0]), "=r"(bb[1])
                : "r"(bbase2 + s * 32));
            mma_f16(acc[2], aa, bb);
        }
    }
}

// 3-stage ring, depth-2 prefetch, ONE sync per chunk.
template<int NBLK, int R>
__device__ __forceinline__ void run_phase(unsigned smb,
        const __half* A, int ldA, const __half* W, int ldW, int khalf,
        float acc[4][4], int tid, int kw, int m0, int lane) {
    const int nit = khalf / CHH;
    load_stage<R>(smb, 0, A, ldA, W, ldW, khalf, 0, tid);
    if (nit > 1) load_stage<R>(smb, 1, A, ldA, W, ldW, khalf, CHH, tid);
    int st = 0;
    for (int it = 0; it < nit; it++) {
        if (it + 1 < nit)
            asm volatile("cp.async.wait_group 1;" ::: "memory");
        else
            asm volatile("cp.async.wait_group 0;" ::: "memory");
        __syncthreads();
        if (it + 2 < nit) {
            int slot = st + 2; if (slot >= 3) slot -= 3;
            load_stage<R>(smb, slot, A, ldA, W, ldW, khalf, (it + 2) * CHH, tid);
        }
        compute_chunk<NBLK>(smb, st, kw, m0, lane, acc);
        if (++st == 3) st = 0;
    }
}

__device__ __forceinline__ void reduce_blocks(float* red, float acc[4][4],
        int kw, int mw, int lane, int b0, int b1) {
    if (kw == 1)
        for (int blk = b0; blk <= b1; blk++)
            #pragma unroll
            for (int q = 0; q < 4; q++)
                red[((mw * 4 + blk) * 32 + lane) * 4 + q] = acc[blk][q];
    __syncthreads();
    if (kw == 0)
        for (int blk = b0; blk <= b1; blk++)
            #pragma unroll
            for (int q = 0; q < 4; q++)
                acc[blk][q] += red[((mw * 4 + blk) * 32 + lane) * 4 + q];
}

// distributed-arrival barrier (R14 best): 8 counters 256B apart; 16 arrivals each
__device__ __forceinline__ void gridbar(unsigned* barno, int cta, int tid) {
    __syncthreads();
    (*barno)++;
    const unsigned target = 16u * (*barno);
    if (tid == 0) {
        __threadfence();
        atomicAdd(&g_bar8[(cta & 7) * 64], 1u);
    }
    if (tid < 8) {
        const unsigned* p = &g_bar8[tid * 64];
        unsigned v;
        do {
            asm volatile("ld.acquire.gpu.global.u32 %0, [%1];" : "=r"(v) : "l"(p) : "memory");
        } while (v < target);
    }
    __syncthreads();
}

// ------------------------- persistent kernel -------------------------
__global__ void __launch_bounds__(NTHR, 1) rnn_persist(
        const float* __restrict__ X, const float* __restrict__ Mm,
        const float* __restrict__ bout, float* __restrict__ out) {
    extern __shared__ char smraw[];
    __half* sm = (__half*)smraw;
    float* red = (float*)(smraw + RED_BYTE_OFF);
    unsigned smb = (unsigned)__cvta_generic_to_shared(smraw);
    const int cta = blockIdx.x, tid = threadIdx.x;
    const int warp = tid >> 5, lane = tid & 31;
    const int mw = warp & 3, kw = warp >> 2;
    const int m0 = mw << 4, r = lane >> 2, c = lane & 3;
    const __half* WP1 = g_WP1 + cta * 26 * HH;
    const __half* WP2 = g_WP2 + cta * 24 * DD;
    const __half* WP3 = g_WP3 + cta * 24 * HH;
    const float* B0p = g_B0 + cta * 24;
    const float* B1p = g_B1 + cta * 24;
    const int u0 = cta * 8, d0 = cta * 2;
    unsigned barno = 0;
    float acc[4][4];
    const bool est_thr = (kw == 0 && c == 0);

    // zero the W pad rows (26..31) of every stage/kw once (never overwritten)
    for (int i = tid; i < 3 * 2 * 6 * SROW_H; i += NTHR) {
        int st = i / (2 * 6 * SROW_H), rem = i % (2 * 6 * SROW_H);
        int kwz = rem / (6 * SROW_H), rem2 = rem % (6 * SROW_H);
        sm[Ws_idx(st, kwz, 26 + rem2 / SROW_H, rem2 % SROW_H)] = __float2half_rn(0.0f);
    }
    __syncthreads();

    for (int t = 0;; t++) {
        if (t == TT) {   // h_final -> out tail (fp32 copy)
            for (int i = tid; i < 512; i += NTHR)
                out[BB * TT * DD + cta * 512 + i] = g_hf[cta * 512 + i];
        }
        // prefetch X/Mm for the est epilogue (known from t alone)
        float xv[2][2], mv[2][2];
        if (est_thr && t < TT) {
            #pragma unroll
            for (int half = 0; half < 2; half++) {
                int b = m0 + r + half * 8;
                #pragma unroll
                for (int j = 0; j < 2; j++) {
                    int xi = (b * TT + t) * DD + d0 + j;
                    xv[half][j] = X[xi];
                    mv[half][j] = Mm[xi];
                }
            }
        }
        // ---- P1: [gates0-h (24) | est (2, block 3)] = h @ WP1^T (k=1024) ----
        // blocks 0-2 stay per-kw partials (reduced once after P2); only block 3 here.
        #pragma unroll
        for (int blk = 0; blk < 4; blk++)
            #pragma unroll
            for (int q = 0; q < 4; q++) acc[blk][q] = 0.0f;
        run_phase<4, 26>(smb, g_h, HH, WP1, HH, 512, acc, tid, kw, m0, lane);
        reduce_blocks(red, acc, kw, mw, lane, 3, 3);
        if (est_thr) {   // est epilogue: cols 0,1 of block 3
            #pragma unroll
            for (int half = 0; half < 2; half++) {
                int b = m0 + r + half * 8;
                float ev[2];
                #pragma unroll
                for (int j = 0; j < 2; j++) {
                    int d = d0 + j;
                    float e = acc[3][half * 2 + j] + bout[d];
                    if (t > 0) out[(b * TT + (t - 1)) * DD + d] = e;
                    if (t < TT) {
                        float m = mv[half][j];
                        ev[j] = m * xv[half][j] + (1.0f - m) * e;
                    }
                }
                if (t < TT)
                    *(__half2*)&g_imp[b * DD + d0] = __floats2half2_rn(ev[0], ev[1]);
            }
        }
        if (t == TT) break;
        gridbar(&barno, cta, tid);

        // ---- P2: gates0 += imp @ WP2^T (k=256), act0 -> h0 ----
        run_phase<3, 24>(smb, g_imp, DD, WP2, DD, 128, acc, tid, kw, m0, lane);
        reduce_blocks(red, acc, kw, mw, lane, 0, 2);
        if (kw == 0) {
            #pragma unroll
            for (int half = 0; half < 2; half++) {
                int b = m0 + r + half * 8;
                float hv[2];
                #pragma unroll
                for (int j = 0; j < 2; j++) {
                    int col = 2 * c + j;
                    float gi = acc[0][half * 2 + j] + B0p[col];
                    float gg = acc[1][half * 2 + j] + B0p[8 + col];
                    float go = acc[2][half * 2 + j] + B0p[16 + col];
                    float si = 1.0f / (1.0f + expf(-gi));
                    float so = 1.0f / (1.0f + expf(-go));
                    hv[j] = so * tanhf(si * tanhf(gg));
                }
                *(__half2*)&g_h0[b * HH + u0 + 2 * c] = __floats2half2_rn(hv[0], hv[1]);
            }
        }
        gridbar(&barno, cta, tid);

        // ---- P3: gates1 = h0 @ WP3^T (k=1024), act1 -> h ----
        #pragma unroll
        for (int blk = 0; blk < 3; blk++)
            #pragma unroll
            for (int q = 0; q < 4; q++) acc[blk][q] = 0.0f;
        run_phase<3, 24>(smb, g_h0, HH, WP3, HH, 512, acc, tid, kw, m0, lane);
        reduce_blocks(red, acc, kw, mw, lane, 0, 2);
        if (kw == 0) {
            #pragma unroll
            for (int half = 0; half < 2; half++) {
                int b = m0 + r + half * 8;
                float hv[2];
                #pragma unroll
                for (int j = 0; j < 2; j++) {
                    int col = 2 * c + j;
                    float gi = acc[0][half * 2 + j] + B1p[col];
                    float gg = acc[1][half * 2 + j] + B1p[8 + col];
                    float go = acc[2][half * 2 + j] + B1p[16 + col];
                    float si = 1.0f / (1.0f + expf(-gi));
                    float so = 1.0f / (1.0f + expf(-go));
                    hv[j] = so * tanhf(si * tanhf(gg));
                }
                *(__half2*)&g_h[b * HH + u0 + 2 * c] = __floats2half2_rn(hv[0], hv[1]);
                if (t == TT - 1)
                    *(float2*)&g_hf[b * HH + u0 + 2 * c] = make_float2(hv[0], hv[1]);
            }
        }
        gridbar(&barno, cta, tid);
    }
}

// ------------------------------- launch --------------------------------
extern "C" void kernel_launch(void* const* d_in, const int* in_sizes, int n_in,
                              void* d_out, int out_size) {
    const float* X    = (const float*)d_in[0];
    const float* Mm   = (const float*)d_in[1];
    const float* Wih0 = (const float*)d_in[2];
    const float* Whh0 = (const float*)d_in[3];
    const float* bih0 = (const float*)d_in[4];
    const float* bhh0 = (const float*)d_in[5];
    const float* Wih1 = (const float*)d_in[6];
    const float* Whh1 = (const float*)d_in[7];
    const float* bih1 = (const float*)d_in[8];
    const float* bhh1 = (const float*)d_in[9];
    const float* Wout = (const float*)d_in[10];
    const float* bout = (const float*)d_in[11];
    float* out = (float*)d_out;

    cudaFuncSetAttribute(rnn_persist, cudaFuncAttributeMaxDynamicSharedMemorySize,
                         SMEM_BYTES);

    pack_all<<<(PACK_TOT + 255) / 256, 256>>>(Wih0, Whh0, bih0, bhh0,
                                              Wih1, Whh1, bih1, bhh1, Wout);
    rnn_persist<<<NCTA, NTHR, SMEM_BYTES>>>(X, Mm, bout, out);
}